// round 8
// baseline (speedup 1.0000x reference)
#include <cuda_runtime.h>
#include <cstdint>

// ReconstructionHead fused: h = x@W1^T + b1 ; LayerNorm ; ReLU ; out[r] = h·Wout[t] + bout[t]
// tf32 tcgen05 GEMM, M=128/CTA, N=512 in TMEM, K=512 in 16 x BK=32 double-buffered tiles.
// Per-buffer mbarriers (2) so a barrier can never run 2 phases ahead of a waiter.

static constexpr int THREADS = 256;
static constexpr int NKT = 16;          // 512 / 32
static constexpr float EPSV = 1e-5f;

// shared memory layout (dynamic) — tcgen05 path
static constexpr int SM_TMEM = 0;
static constexpr int SM_MBAR0 = 8;                  // mbar for buffer 0
static constexpr int SM_MBAR1 = 16;                 // mbar for buffer 1
static constexpr int SM_RED0 = 32;                  // 256 floats
static constexpr int SM_RED1 = SM_RED0 + 1024;      // 256 floats
static constexpr int SM_B1v  = SM_RED1 + 1024;      // 512 floats
static constexpr int SM_G    = SM_B1v + 2048;       // 512 floats
static constexpr int SM_BE   = SM_G + 2048;         // 512 floats
static constexpr int SM_A0   = 16384;               // 2 x 16KB A tiles (128 x 32 tf32)
static constexpr int SM_BT0  = 49152;               // 2 x 64KB B tiles (512 x 32 tf32)
static constexpr int SMEM_TOTAL = SM_BT0 + 2 * 65536;  // 180224 bytes

// Arch-specific ("a") feature fence: tcgen05/TMEM only exist on sm_10xa passes.
#if defined(__CUDA_ARCH__) && (defined(__CUDA_ARCH_FEAT_SM103_ALL) || \
                               defined(__CUDA_ARCH_FEAT_SM100_ALL) || \
                               defined(__CUDA_ARCH_FEAT_SM101_ALL) || \
                               defined(__CUDA_ARCH_SPECIFIC__)     || \
                               defined(__CUDA_ARCH_FAMILY_SPECIFIC__))
#define RH_TCGEN05 1
#else
#define RH_TCGEN05 0
#endif

#if RH_TCGEN05

// idesc: c=F32(1<<4), a=TF32(2<<7), b=TF32(2<<10), N=256 (32<<17), M=128 (8<<24)
static constexpr uint32_t IDESC_TF32 =
    (1u << 4) | (2u << 7) | (2u << 10) | (32u << 17) | (8u << 24);

// SW128 K-major descriptor base: layout=2, version=1, SBO=64 (1024B atom), LBO=1
static constexpr uint64_t DESC_BASE_SW128 =
    (uint64_t(2) << 61) | (uint64_t(1) << 46) | (uint64_t(64) << 32) | (uint64_t(1) << 16);

static __device__ __forceinline__ uint32_t smem_u32(const void* p) {
    uint32_t a;
    asm("{ .reg .u64 t; cvta.to.shared.u64 t, %1; cvt.u32.u64 %0, t; }" : "=r"(a) : "l"(p));
    return a;
}
static __device__ __forceinline__ uint64_t make_desc(uint32_t addr) {
    return DESC_BASE_SW128 | ((uint64_t)(addr >> 4) & 0x3FFF);
}
static __device__ __forceinline__ uint32_t f2tf(float f) {
    uint32_t u; asm("cvt.rna.tf32.f32 %0, %1;" : "=r"(u) : "f"(f)); return u;
}
static __device__ __forceinline__ bool elect_one() {
    uint32_t p;
    asm volatile("{\n\t.reg .pred P;\n\telect.sync _|P, 0xFFFFFFFF;\n\tselp.b32 %0, 1, 0, P;\n\t}"
                 : "=r"(p));
    return p != 0;
}
static __device__ __forceinline__ void mbar_init(uint32_t a, uint32_t cnt) {
    asm volatile("mbarrier.init.shared.b64 [%0], %1;" :: "r"(a), "r"(cnt) : "memory");
}
static __device__ __forceinline__ void mbar_inval(uint32_t a) {
    asm volatile("mbarrier.inval.shared.b64 [%0];" :: "r"(a) : "memory");
}
static __device__ __forceinline__ void mbar_wait(uint32_t a, uint32_t parity) {
    asm volatile(
        "{\n\t.reg .pred P;\n\t"
        "W%=:\n\t"
        "mbarrier.try_wait.parity.acquire.cta.shared::cta.b64 P, [%0], %1, 0x989680;\n\t"
        "@P bra.uni D%=;\n\t"
        "bra.uni W%=;\n\t"
        "D%=:\n\t}"
        :: "r"(a), "r"(parity) : "memory");
}
static __device__ __forceinline__ void tmem_alloc_512(uint32_t smem_dst) {
    asm volatile("tcgen05.alloc.cta_group::1.sync.aligned.shared::cta.b32 [%0], %1;"
                 :: "r"(smem_dst), "r"(512u) : "memory");
}
static __device__ __forceinline__ void tmem_dealloc_512(uint32_t tmem) {
    asm volatile("tcgen05.dealloc.cta_group::1.sync.aligned.b32 %0, %1;" :: "r"(tmem), "r"(512u));
}
static __device__ __forceinline__ void tmem_relinquish() {
    asm volatile("tcgen05.relinquish_alloc_permit.cta_group::1.sync.aligned;");
}
static __device__ __forceinline__ void mma_tf32_ss(uint32_t d, uint64_t ad, uint64_t bd,
                                                   uint32_t idesc, uint32_t en) {
    asm volatile(
        "{\n\t.reg .pred p;\n\tsetp.ne.u32 p, %4, 0;\n\t"
        "tcgen05.mma.cta_group::1.kind::tf32 [%0], %1, %2, %3, p;\n\t}"
        :: "r"(d), "l"(ad), "l"(bd), "r"(idesc), "r"(en) : "memory");
}
static __device__ __forceinline__ void mma_commit(uint32_t mbar) {
    asm volatile("tcgen05.commit.cta_group::1.mbarrier::arrive::one.shared::cluster.b64 [%0];"
                 :: "r"(mbar) : "memory");
}
static __device__ __forceinline__ void tmem_wait_ld() {
    asm volatile("tcgen05.wait::ld.sync.aligned;" ::: "memory");
}

#define LDTM_X32(r, addr)                                                      \
    asm volatile(                                                              \
        "tcgen05.ld.sync.aligned.32x32b.x32.b32 "                              \
        "{%0, %1, %2, %3, %4, %5, %6, %7, "                                    \
        " %8, %9, %10, %11, %12, %13, %14, %15, "                              \
        " %16, %17, %18, %19, %20, %21, %22, %23, "                            \
        " %24, %25, %26, %27, %28, %29, %30, %31}, [%32];"                     \
        : "=r"((r)[0]),  "=r"((r)[1]),  "=r"((r)[2]),  "=r"((r)[3]),           \
          "=r"((r)[4]),  "=r"((r)[5]),  "=r"((r)[6]),  "=r"((r)[7]),           \
          "=r"((r)[8]),  "=r"((r)[9]),  "=r"((r)[10]), "=r"((r)[11]),          \
          "=r"((r)[12]), "=r"((r)[13]), "=r"((r)[14]), "=r"((r)[15]),          \
          "=r"((r)[16]), "=r"((r)[17]), "=r"((r)[18]), "=r"((r)[19]),          \
          "=r"((r)[20]), "=r"((r)[21]), "=r"((r)[22]), "=r"((r)[23]),          \
          "=r"((r)[24]), "=r"((r)[25]), "=r"((r)[26]), "=r"((r)[27]),          \
          "=r"((r)[28]), "=r"((r)[29]), "=r"((r)[30]), "=r"((r)[31])           \
        : "r"(addr))

// Stage ROWS x 32 fp32 tile (gmem row stride 512 floats) into SW128-swizzled smem as tf32.
template <int ROWS>
static __device__ __forceinline__ void stage_tile(char* dst, const float* __restrict__ g, int tid) {
#pragma unroll
    for (int idx = tid; idx < ROWS * 8; idx += THREADS) {
        int row = idx >> 3, v = idx & 7;
        float4 d = *reinterpret_cast<const float4*>(g + (size_t)row * 512 + (v << 2));
        uint32_t off = (uint32_t)((row << 7) + (v << 4));
        off ^= (off >> 3) & 0x70;
        uint4 t;
        t.x = f2tf(d.x); t.y = f2tf(d.y); t.z = f2tf(d.z); t.w = f2tf(d.w);
        *reinterpret_cast<uint4*>(dst + off) = t;
    }
}

#endif  // RH_TCGEN05

__global__ void __launch_bounds__(THREADS, 1)
fused_head_kernel(const float* __restrict__ x, const float* __restrict__ W1,
                  const float* __restrict__ b1, const float* __restrict__ gamma,
                  const float* __restrict__ beta, const float* __restrict__ Wout,
                  const float* __restrict__ bout, float* __restrict__ out)
{
    extern __shared__ char smem[];
    const int tid = threadIdx.x;
    const int wid = tid >> 5;
    const int lid = tid & 31;
    const int bx = blockIdx.x;
    const int bb = bx >> 2;               // batch index
    const int t0 = (bx & 3) << 7;         // first t of this CTA's 128 rows
    const float* xbase = x + ((size_t)bb * 513 + t0) * 512;

#if RH_TCGEN05
    const uint32_t sb = smem_u32(smem);

    if (wid == 0) tmem_alloc_512(sb + SM_TMEM);
    if (tid == 0) {
        mbar_init(sb + SM_MBAR0, 1);
        mbar_init(sb + SM_MBAR1, 1);
    }

    float* smb1 = (float*)(smem + SM_B1v);
    float* smg  = (float*)(smem + SM_G);
    float* smbe = (float*)(smem + SM_BE);
#pragma unroll
    for (int i = tid; i < 512; i += THREADS) {
        smb1[i] = b1[i];
        smg[i]  = gamma[i];
        smbe[i] = beta[i];
    }

    // prologue: stage K-tile 0 into buffer 0
    stage_tile<128>(smem + SM_A0, xbase, tid);
    stage_tile<512>(smem + SM_BT0, W1, tid);
    __syncthreads();
    const uint32_t tmem = *(const uint32_t*)(smem + SM_TMEM);

    // per-buffer phase counters (identical on all threads)
    uint32_t ph0 = 0, ph1 = 0;

    // main K loop: issue MMAs for tile k (buffer k&1), overlap staging of tile k+1.
    // mbar[j] is committed only for buffer j; the wait on mbar[jn]'s phase p strictly
    // precedes (via staging __syncthreads) the commit of its phase p+1 — no parity reuse hazard.
    for (int k = 0; k < NKT; k++) {
        const int j = k & 1;
        if (wid == 0) {
            asm volatile("fence.proxy.async.shared::cta;" ::: "memory");
            if (elect_one()) {
                const uint64_t ad = make_desc(sb + SM_A0 + j * 16384);
                const uint64_t bd = make_desc(sb + SM_BT0 + j * 65536);
#pragma unroll
                for (int c = 0; c < 4; c++) {             // 4 K-steps of 8 within BK=32
                    const uint32_t en = (k | c) ? 1u : 0u;
                    mma_tf32_ss(tmem,       ad + c * 2, bd + c * 2,        IDESC_TF32, en);
                    mma_tf32_ss(tmem + 256, ad + c * 2, bd + 2048 + c * 2, IDESC_TF32, en);
                }
                mma_commit(sb + (j ? SM_MBAR1 : SM_MBAR0));
            }
        }
        if (k + 1 < NKT) {
            const int jn = (k + 1) & 1;
            if (k >= 1) {                  // buffer jn last committed in iteration k-1
                if (jn == 0) { mbar_wait(sb + SM_MBAR0, ph0 & 1); ph0++; }
                else         { mbar_wait(sb + SM_MBAR1, ph1 & 1); ph1++; }
            }
            stage_tile<128>(smem + SM_A0 + jn * 16384, xbase + (size_t)(k + 1) * 32, tid);
            stage_tile<512>(smem + SM_BT0 + jn * 65536, W1 + (size_t)(k + 1) * 32, tid);
            __syncthreads();
        }
    }
    // final commit was iteration 15 -> buffer 1 -> mbar1 phase ph1
    mbar_wait(sb + SM_MBAR1, ph1 & 1);
    asm volatile("tcgen05.fence::after_thread_sync;" ::: "memory");

    // ---- fused epilogue: bias + LN stats + normalize + ReLU + Wout dot ----
    const int sub  = wid & 3;            // TMEM subpartition
    const int half = wid >> 2;           // column half (0: cols 0-255, 1: 256-511)
    const int lrow = (sub << 5) + lid;   // row within CTA tile (0..127)
    const int trow = t0 + lrow;
    const uint32_t tb = tmem + half * 256;
    float* red0 = (float*)(smem + SM_RED0);
    float* red1 = (float*)(smem + SM_RED1);

    // pass 1: sum / sumsq over this warp's column half
    float sum = 0.f, sq = 0.f;
#pragma unroll
    for (int cb = 0; cb < 256; cb += 32) {
        uint32_t r[32];
        LDTM_X32(r, tb + cb);
        tmem_wait_ld();
#pragma unroll
        for (int i = 0; i < 32; i++) {
            float v = __uint_as_float(r[i]) + smb1[half * 256 + cb + i];
            sum += v;
            sq  = fmaf(v, v, sq);
        }
    }
    red0[half * 128 + lrow] = sum;
    red1[half * 128 + lrow] = sq;
    __syncthreads();
    const float s  = red0[lrow] + red0[128 + lrow];
    const float q  = red1[lrow] + red1[128 + lrow];
    const float mu = s * (1.f / 512.f);
    const float var = q * (1.f / 512.f) - mu * mu;
    const float rstd = rsqrtf(var + EPSV);

    // pass 2: normalize, ReLU, dot with Wout[trow]
    float acc = 0.f;
    const float4* wr = (const float4*)(Wout + (size_t)trow * 512 + half * 256);
#pragma unroll
    for (int cb = 0; cb < 256; cb += 32) {
        uint32_t r[32];
        LDTM_X32(r, tb + cb);
        tmem_wait_ld();
#pragma unroll
        for (int i4 = 0; i4 < 8; i4++) {
            float4 w = wr[(cb >> 2) + i4];
#pragma unroll
            for (int u = 0; u < 4; u++) {
                const int e = half * 256 + cb + i4 * 4 + u;
                float v = __uint_as_float(r[i4 * 4 + u]) + smb1[e];
                float n = fmaf((v - mu) * rstd, smg[e], smbe[e]);
                n = fmaxf(n, 0.f);
                const float wv = (u == 0) ? w.x : (u == 1) ? w.y : (u == 2) ? w.z : w.w;
                acc = fmaf(n, wv, acc);
            }
        }
    }
    __syncthreads();                 // red0 reads above complete before overwrite
    red0[half * 128 + lrow] = acc;
    __syncthreads();
    if (half == 0) {
        out[(size_t)bx * 128 + lrow] = red0[lrow] + red0[128 + lrow] + bout[trow];
    }

    __syncthreads();
    if (tid == 0) {
        mbar_inval(sb + SM_MBAR0);
        mbar_inval(sb + SM_MBAR1);
    }
    if (wid == 0) {
        tmem_relinquish();
        tmem_dealloc_512(tmem);
    }

#else  // ---------- SIMT fp32 fallback (non-arch-specific device passes) ----------

    float* xs = (float*)smem;              // 16 x 512 floats
    float* hs = xs + 16 * 512;             // 16 x 512 floats

    for (int rc = 0; rc < 128; rc += 16) {
        // stage 16 rows of x
        for (int i = tid; i < 16 * 512; i += THREADS)
            xs[i] = xbase[((size_t)(rc + (i >> 9))) * 512 + (i & 511)];
        __syncthreads();

        // h[r][c] = xs[r]·W1[c] + b1[c]
        for (int idx = tid; idx < 16 * 512; idx += THREADS) {
            const int c = idx >> 4;        // 0..511
            const int r = idx & 15;        // 0..15
            const float* xr = xs + r * 512;
            const float* wc = W1 + (size_t)c * 512;
            float acc = 0.f;
#pragma unroll 4
            for (int k2 = 0; k2 < 512; k2++) acc = fmaf(xr[k2], wc[k2], acc);
            hs[r * 512 + c] = acc + b1[c];
        }
        __syncthreads();

        // LN + ReLU + dot with Wout: one warp per row
        for (int rr = wid; rr < 16; rr += 8) {
            const float* hr = hs + rr * 512;
            float s = 0.f, q = 0.f;
            for (int k2 = lid; k2 < 512; k2 += 32) {
                float v = hr[k2];
                s += v;
                q = fmaf(v, v, q);
            }
#pragma unroll
            for (int off = 16; off; off >>= 1) {
                s += __shfl_xor_sync(0xFFFFFFFFu, s, off);
                q += __shfl_xor_sync(0xFFFFFFFFu, q, off);
            }
            const float mu = s * (1.f / 512.f);
            const float var = q * (1.f / 512.f) - mu * mu;
            const float rstd = rsqrtf(var + EPSV);
            const int trow = t0 + rc + rr;
            float a = 0.f;
            for (int k2 = lid; k2 < 512; k2 += 32) {
                float v = hr[k2];
                float n = fmaf((v - mu) * rstd, gamma[k2], beta[k2]);
                n = fmaxf(n, 0.f);
                a = fmaf(n, Wout[(size_t)trow * 512 + k2], a);
            }
#pragma unroll
            for (int off = 16; off; off >>= 1)
                a += __shfl_xor_sync(0xFFFFFFFFu, a, off);
            if (lid == 0) out[(size_t)bx * 128 + rc + rr] = a + bout[trow];
        }
        __syncthreads();
    }
#endif
}

extern "C" void kernel_launch(void* const* d_in, const int* in_sizes, int n_in,
                              void* d_out, int out_size) {
    (void)in_sizes; (void)n_in; (void)out_size;
    const float* x     = (const float*)d_in[0];
    const float* W1    = (const float*)d_in[1];
    const float* b1    = (const float*)d_in[2];
    const float* gamma = (const float*)d_in[3];
    const float* beta  = (const float*)d_in[4];
    const float* Wout  = (const float*)d_in[5];
    const float* bout  = (const float*)d_in[6];
    float* out = (float*)d_out;

    cudaFuncSetAttribute(fused_head_kernel,
                         cudaFuncAttributeMaxDynamicSharedMemorySize, SMEM_TOTAL);
    fused_head_kernel<<<1024, THREADS, SMEM_TOTAL>>>(x, W1, b1, gamma, beta, Wout, bout, out);
}

// round 9
// speedup vs baseline: 1.4271x; 1.4271x over previous
#include <cuda_runtime.h>
#include <cstdint>

// ReconstructionHead fused: h = x@W1^T + b1 ; LayerNorm ; ReLU ; out[r] = h·Wout[t] + bout[t]
// tf32 tcgen05 GEMM, M=128/CTA, N=512 in TMEM, K=512 in 16 x BK=32 double-buffered tiles.
// 512 threads; register-prefetched staging overlaps LDG latency with MMA; per-buffer mbarriers.

static constexpr int THREADS = 512;
static constexpr int NKT = 16;          // 512 / 32
static constexpr float EPSV = 1e-5f;

// shared memory layout (dynamic) — tcgen05 path
static constexpr int SM_TMEM = 0;
static constexpr int SM_MBAR0 = 8;                  // mbar for buffer 0
static constexpr int SM_MBAR1 = 16;                 // mbar for buffer 1
static constexpr int SM_RED0 = 32;                  // 512 floats
static constexpr int SM_RED1 = SM_RED0 + 2048;      // 512 floats
static constexpr int SM_B1v  = SM_RED1 + 2048;      // 512 floats
static constexpr int SM_G    = SM_B1v + 2048;       // 512 floats
static constexpr int SM_BE   = SM_G + 2048;         // 512 floats
static constexpr int SM_A0   = 16384;               // 2 x 16KB A tiles (128 x 32 tf32)
static constexpr int SM_BT0  = 49152;               // 2 x 64KB B tiles (512 x 32 tf32)
static constexpr int SMEM_TOTAL = SM_BT0 + 2 * 65536;  // 180224 bytes

// Arch-specific ("a") feature fence: tcgen05/TMEM only exist on sm_10xa passes.
#if defined(__CUDA_ARCH__) && (defined(__CUDA_ARCH_FEAT_SM103_ALL) || \
                               defined(__CUDA_ARCH_FEAT_SM100_ALL) || \
                               defined(__CUDA_ARCH_FEAT_SM101_ALL) || \
                               defined(__CUDA_ARCH_SPECIFIC__)     || \
                               defined(__CUDA_ARCH_FAMILY_SPECIFIC__))
#define RH_TCGEN05 1
#else
#define RH_TCGEN05 0
#endif

#if RH_TCGEN05

// idesc: c=F32(1<<4), a=TF32(2<<7), b=TF32(2<<10), N=256 (32<<17), M=128 (8<<24)
static constexpr uint32_t IDESC_TF32 =
    (1u << 4) | (2u << 7) | (2u << 10) | (32u << 17) | (8u << 24);

// SW128 K-major descriptor base: layout=2, version=1, SBO=64 (1024B atom), LBO=1
static constexpr uint64_t DESC_BASE_SW128 =
    (uint64_t(2) << 61) | (uint64_t(1) << 46) | (uint64_t(64) << 32) | (uint64_t(1) << 16);

static __device__ __forceinline__ uint32_t smem_u32(const void* p) {
    uint32_t a;
    asm("{ .reg .u64 t; cvta.to.shared.u64 t, %1; cvt.u32.u64 %0, t; }" : "=r"(a) : "l"(p));
    return a;
}
static __device__ __forceinline__ uint64_t make_desc(uint32_t addr) {
    return DESC_BASE_SW128 | ((uint64_t)(addr >> 4) & 0x3FFF);
}
static __device__ __forceinline__ uint32_t f2tf(float f) {
    uint32_t u; asm("cvt.rna.tf32.f32 %0, %1;" : "=r"(u) : "f"(f)); return u;
}
static __device__ __forceinline__ bool elect_one() {
    uint32_t p;
    asm volatile("{\n\t.reg .pred P;\n\telect.sync _|P, 0xFFFFFFFF;\n\tselp.b32 %0, 1, 0, P;\n\t}"
                 : "=r"(p));
    return p != 0;
}
static __device__ __forceinline__ void mbar_init(uint32_t a, uint32_t cnt) {
    asm volatile("mbarrier.init.shared.b64 [%0], %1;" :: "r"(a), "r"(cnt) : "memory");
}
static __device__ __forceinline__ void mbar_inval(uint32_t a) {
    asm volatile("mbarrier.inval.shared.b64 [%0];" :: "r"(a) : "memory");
}
static __device__ __forceinline__ void mbar_wait(uint32_t a, uint32_t parity) {
    asm volatile(
        "{\n\t.reg .pred P;\n\t"
        "W%=:\n\t"
        "mbarrier.try_wait.parity.acquire.cta.shared::cta.b64 P, [%0], %1, 0x989680;\n\t"
        "@P bra.uni D%=;\n\t"
        "bra.uni W%=;\n\t"
        "D%=:\n\t}"
        :: "r"(a), "r"(parity) : "memory");
}
static __device__ __forceinline__ void tmem_alloc_512(uint32_t smem_dst) {
    asm volatile("tcgen05.alloc.cta_group::1.sync.aligned.shared::cta.b32 [%0], %1;"
                 :: "r"(smem_dst), "r"(512u) : "memory");
}
static __device__ __forceinline__ void tmem_dealloc_512(uint32_t tmem) {
    asm volatile("tcgen05.dealloc.cta_group::1.sync.aligned.b32 %0, %1;" :: "r"(tmem), "r"(512u));
}
static __device__ __forceinline__ void tmem_relinquish() {
    asm volatile("tcgen05.relinquish_alloc_permit.cta_group::1.sync.aligned;");
}
static __device__ __forceinline__ void mma_tf32_ss(uint32_t d, uint64_t ad, uint64_t bd,
                                                   uint32_t idesc, uint32_t en) {
    asm volatile(
        "{\n\t.reg .pred p;\n\tsetp.ne.u32 p, %4, 0;\n\t"
        "tcgen05.mma.cta_group::1.kind::tf32 [%0], %1, %2, %3, p;\n\t}"
        :: "r"(d), "l"(ad), "l"(bd), "r"(idesc), "r"(en) : "memory");
}
static __device__ __forceinline__ void mma_commit(uint32_t mbar) {
    asm volatile("tcgen05.commit.cta_group::1.mbarrier::arrive::one.shared::cluster.b64 [%0];"
                 :: "r"(mbar) : "memory");
}
static __device__ __forceinline__ void tmem_wait_ld() {
    asm volatile("tcgen05.wait::ld.sync.aligned;" ::: "memory");
}

#define LDTM_X32(r, addr)                                                      \
    asm volatile(                                                              \
        "tcgen05.ld.sync.aligned.32x32b.x32.b32 "                              \
        "{%0, %1, %2, %3, %4, %5, %6, %7, "                                    \
        " %8, %9, %10, %11, %12, %13, %14, %15, "                              \
        " %16, %17, %18, %19, %20, %21, %22, %23, "                            \
        " %24, %25, %26, %27, %28, %29, %30, %31}, [%32];"                     \
        : "=r"((r)[0]),  "=r"((r)[1]),  "=r"((r)[2]),  "=r"((r)[3]),           \
          "=r"((r)[4]),  "=r"((r)[5]),  "=r"((r)[6]),  "=r"((r)[7]),           \
          "=r"((r)[8]),  "=r"((r)[9]),  "=r"((r)[10]), "=r"((r)[11]),          \
          "=r"((r)[12]), "=r"((r)[13]), "=r"((r)[14]), "=r"((r)[15]),          \
          "=r"((r)[16]), "=r"((r)[17]), "=r"((r)[18]), "=r"((r)[19]),          \
          "=r"((r)[20]), "=r"((r)[21]), "=r"((r)[22]), "=r"((r)[23]),          \
          "=r"((r)[24]), "=r"((r)[25]), "=r"((r)[26]), "=r"((r)[27]),          \
          "=r"((r)[28]), "=r"((r)[29]), "=r"((r)[30]), "=r"((r)[31])           \
        : "r"(addr))

// Per-thread staging slots: A tile (128x32 fp32) = 1024 float4 -> 2/thread;
// B tile (512x32 fp32) = 4096 float4 -> 8/thread.
static __device__ __forceinline__ void ldg_tile(float4 (&ra)[2], float4 (&rb)[8],
                                                const float* __restrict__ xg,
                                                const float* __restrict__ wg, int tid) {
#pragma unroll
    for (int i = 0; i < 2; i++) {
        const int s = tid + i * THREADS;         // 0..1023
        ra[i] = *reinterpret_cast<const float4*>(xg + (size_t)(s >> 3) * 512 + ((s & 7) << 2));
    }
#pragma unroll
    for (int i = 0; i < 8; i++) {
        const int s = tid + i * THREADS;         // 0..4095
        rb[i] = *reinterpret_cast<const float4*>(wg + (size_t)(s >> 3) * 512 + ((s & 7) << 2));
    }
}
static __device__ __forceinline__ void sts_slot(char* base, int s, const float4& d) {
    uint32_t off = (uint32_t)(((s >> 3) << 7) + ((s & 7) << 4));
    off ^= (off >> 3) & 0x70;
    uint4 t;
    t.x = f2tf(d.x); t.y = f2tf(d.y); t.z = f2tf(d.z); t.w = f2tf(d.w);
    *reinterpret_cast<uint4*>(base + off) = t;
}
static __device__ __forceinline__ void sts_tile(char* adst, char* bdst,
                                                const float4 (&ra)[2], const float4 (&rb)[8],
                                                int tid) {
#pragma unroll
    for (int i = 0; i < 2; i++) sts_slot(adst, tid + i * THREADS, ra[i]);
#pragma unroll
    for (int i = 0; i < 8; i++) sts_slot(bdst, tid + i * THREADS, rb[i]);
}

#endif  // RH_TCGEN05

__global__ void __launch_bounds__(THREADS, 1)
fused_head_kernel(const float* __restrict__ x, const float* __restrict__ W1,
                  const float* __restrict__ b1, const float* __restrict__ gamma,
                  const float* __restrict__ beta, const float* __restrict__ Wout,
                  const float* __restrict__ bout, float* __restrict__ out)
{
    extern __shared__ char smem[];
    const int tid = threadIdx.x;
    const int wid = tid >> 5;
    const int lid = tid & 31;
    const int bx = blockIdx.x;
    const int bb = bx >> 2;               // batch index
    const int t0 = (bx & 3) << 7;         // first t of this CTA's 128 rows
    const float* xbase = x + ((size_t)bb * 513 + t0) * 512;

#if RH_TCGEN05
    const uint32_t sb = smem_u32(smem);

    if (wid == 0) tmem_alloc_512(sb + SM_TMEM);
    if (tid == 0) {
        mbar_init(sb + SM_MBAR0, 1);
        mbar_init(sb + SM_MBAR1, 1);
    }

    float* smb1 = (float*)(smem + SM_B1v);
    float* smg  = (float*)(smem + SM_G);
    float* smbe = (float*)(smem + SM_BE);
    if (tid < 512) {
        smb1[tid] = b1[tid];
        smg[tid]  = gamma[tid];
        smbe[tid] = beta[tid];
    }

    // prologue: stage K-tile 0 into buffer 0
    float4 ra[2], rb[8];
    ldg_tile(ra, rb, xbase, W1, tid);
    sts_tile(smem + SM_A0, smem + SM_BT0, ra, rb, tid);
    __syncthreads();
    const uint32_t tmem = *(const uint32_t*)(smem + SM_TMEM);

    // per-buffer phase counters (identical on all threads)
    uint32_t ph0 = 0, ph1 = 0;

    // main K loop. Iter k: prefetch LDG for tile k+1 (overlaps MMA k), issue MMA k from
    // buffer k&1, wait buffer (k+1)&1 free (commit from iter k-1), STS, sync.
    for (int k = 0; k < NKT; k++) {
        const int j = k & 1;
        if (k + 1 < NKT)
            ldg_tile(ra, rb, xbase + (size_t)(k + 1) * 32, W1 + (size_t)(k + 1) * 32, tid);
        if (wid == 0) {
            asm volatile("fence.proxy.async.shared::cta;" ::: "memory");
            if (elect_one()) {
                const uint64_t ad = make_desc(sb + SM_A0 + j * 16384);
                const uint64_t bd = make_desc(sb + SM_BT0 + j * 65536);
#pragma unroll
                for (int c = 0; c < 4; c++) {             // 4 K-steps of 8 within BK=32
                    const uint32_t en = (k | c) ? 1u : 0u;
                    mma_tf32_ss(tmem,       ad + c * 2, bd + c * 2,        IDESC_TF32, en);
                    mma_tf32_ss(tmem + 256, ad + c * 2, bd + 2048 + c * 2, IDESC_TF32, en);
                }
                mma_commit(sb + (j ? SM_MBAR1 : SM_MBAR0));
            }
        }
        if (k + 1 < NKT) {
            const int jn = (k + 1) & 1;
            if (k >= 1) {                  // buffer jn last committed in iteration k-1
                if (jn == 0) { mbar_wait(sb + SM_MBAR0, ph0 & 1); ph0++; }
                else         { mbar_wait(sb + SM_MBAR1, ph1 & 1); ph1++; }
            }
            sts_tile(smem + SM_A0 + jn * 16384, smem + SM_BT0 + jn * 65536, ra, rb, tid);
            __syncthreads();
        }
    }
    // final commit was iteration 15 -> buffer 1 -> mbar1 phase ph1
    mbar_wait(sb + SM_MBAR1, ph1 & 1);
    asm volatile("tcgen05.fence::after_thread_sync;" ::: "memory");

    // ---- fused epilogue (16 warps): bias + LN stats + normalize + ReLU + Wout dot ----
    const int sub  = wid & 3;            // TMEM subpartition
    const int qtr  = wid >> 2;           // column quarter (0..3): cols [qtr*128, qtr*128+128)
    const int lrow = (sub << 5) + lid;   // row within CTA tile (0..127)
    const int trow = t0 + lrow;
    const uint32_t tb = tmem + qtr * 128;
    float* red0 = (float*)(smem + SM_RED0);
    float* red1 = (float*)(smem + SM_RED1);

    // pass 1: sum / sumsq over this warp's column quarter
    float sum = 0.f, sq = 0.f;
#pragma unroll
    for (int cb = 0; cb < 128; cb += 32) {
        uint32_t r[32];
        LDTM_X32(r, tb + cb);
        tmem_wait_ld();
#pragma unroll
        for (int i = 0; i < 32; i++) {
            float v = __uint_as_float(r[i]) + smb1[qtr * 128 + cb + i];
            sum += v;
            sq  = fmaf(v, v, sq);
        }
    }
    red0[qtr * 128 + lrow] = sum;
    red1[qtr * 128 + lrow] = sq;
    __syncthreads();
    const float s  = red0[lrow] + red0[128 + lrow] + red0[256 + lrow] + red0[384 + lrow];
    const float q  = red1[lrow] + red1[128 + lrow] + red1[256 + lrow] + red1[384 + lrow];
    const float mu = s * (1.f / 512.f);
    const float var = q * (1.f / 512.f) - mu * mu;
    const float rstd = rsqrtf(var + EPSV);

    // pass 2: normalize, ReLU, dot with Wout[trow]
    float acc = 0.f;
    const float4* wr = (const float4*)(Wout + (size_t)trow * 512 + qtr * 128);
#pragma unroll
    for (int cb = 0; cb < 128; cb += 32) {
        uint32_t r[32];
        LDTM_X32(r, tb + cb);
        tmem_wait_ld();
#pragma unroll
        for (int i4 = 0; i4 < 8; i4++) {
            float4 w = wr[(cb >> 2) + i4];
#pragma unroll
            for (int u = 0; u < 4; u++) {
                const int e = qtr * 128 + cb + i4 * 4 + u;
                float v = __uint_as_float(r[i4 * 4 + u]) + smb1[e];
                float n = fmaf((v - mu) * rstd, smg[e], smbe[e]);
                n = fmaxf(n, 0.f);
                const float wv = (u == 0) ? w.x : (u == 1) ? w.y : (u == 2) ? w.z : w.w;
                acc = fmaf(n, wv, acc);
            }
        }
    }
    __syncthreads();                 // red reads above complete before overwrite
    red0[qtr * 128 + lrow] = acc;
    __syncthreads();
    if (qtr == 0) {
        out[(size_t)bx * 128 + lrow] =
            red0[lrow] + red0[128 + lrow] + red0[256 + lrow] + red0[384 + lrow] + bout[trow];
    }

    __syncthreads();
    if (tid == 0) {
        mbar_inval(sb + SM_MBAR0);
        mbar_inval(sb + SM_MBAR1);
    }
    if (wid == 0) {
        tmem_relinquish();
        tmem_dealloc_512(tmem);
    }

#else  // ---------- SIMT fp32 fallback (non-arch-specific device passes) ----------

    float* xs = (float*)smem;              // 16 x 512 floats
    float* hs = xs + 16 * 512;             // 16 x 512 floats

    for (int rc = 0; rc < 128; rc += 16) {
        // stage 16 rows of x
        for (int i = tid; i < 16 * 512; i += THREADS)
            xs[i] = xbase[((size_t)(rc + (i >> 9))) * 512 + (i & 511)];
        __syncthreads();

        // h[r][c] = xs[r]·W1[c] + b1[c]
        for (int idx = tid; idx < 16 * 512; idx += THREADS) {
            const int c = idx >> 4;        // 0..511
            const int r = idx & 15;        // 0..15
            const float* xr = xs + r * 512;
            const float* wc = W1 + (size_t)c * 512;
            float acc = 0.f;
#pragma unroll 4
            for (int k2 = 0; k2 < 512; k2++) acc = fmaf(xr[k2], wc[k2], acc);
            hs[r * 512 + c] = acc + b1[c];
        }
        __syncthreads();

        // LN + ReLU + dot with Wout: one warp per row
        for (int rr = wid; rr < 16; rr += 16) {
            const float* hr = hs + rr * 512;
            float s = 0.f, q = 0.f;
            for (int k2 = lid; k2 < 512; k2 += 32) {
                float v = hr[k2];
                s += v;
                q = fmaf(v, v, q);
            }
#pragma unroll
            for (int off = 16; off; off >>= 1) {
                s += __shfl_xor_sync(0xFFFFFFFFu, s, off);
                q += __shfl_xor_sync(0xFFFFFFFFu, q, off);
            }
            const float mu = s * (1.f / 512.f);
            const float var = q * (1.f / 512.f) - mu * mu;
            const float rstd = rsqrtf(var + EPSV);
            const int trow = t0 + rc + rr;
            float a = 0.f;
            for (int k2 = lid; k2 < 512; k2 += 32) {
                float v = hr[k2];
                float n = fmaf((v - mu) * rstd, gamma[k2], beta[k2]);
                n = fmaxf(n, 0.f);
                a = fmaf(n, Wout[(size_t)trow * 512 + k2], a);
            }
#pragma unroll
            for (int off = 16; off; off >>= 1)
                a += __shfl_xor_sync(0xFFFFFFFFu, a, off);
            if (lid == 0) out[(size_t)bx * 128 + rc + rr] = a + bout[trow];
        }
        __syncthreads();
    }
#endif
}

extern "C" void kernel_launch(void* const* d_in, const int* in_sizes, int n_in,
                              void* d_out, int out_size) {
    (void)in_sizes; (void)n_in; (void)out_size;
    const float* x     = (const float*)d_in[0];
    const float* W1    = (const float*)d_in[1];
    const float* b1    = (const float*)d_in[2];
    const float* gamma = (const float*)d_in[3];
    const float* beta  = (const float*)d_in[4];
    const float* Wout  = (const float*)d_in[5];
    const float* bout  = (const float*)d_in[6];
    float* out = (float*)d_out;

    cudaFuncSetAttribute(fused_head_kernel,
                         cudaFuncAttributeMaxDynamicSharedMemorySize, SMEM_TOTAL);
    fused_head_kernel<<<1024, THREADS, SMEM_TOTAL>>>(x, W1, b1, gamma, beta, Wout, bout, out);
}

// round 14
// speedup vs baseline: 1.8360x; 1.2866x over previous
#include <cuda_runtime.h>
#include <cuda.h>
#include <cstdint>

// ReconstructionHead fused: h = x@W1^T + b1 ; LayerNorm ; ReLU ; out[r] = h·Wout[t] + bout[t]
// tf32 tcgen05 GEMM, M=128/CTA, N=512 in TMEM, K=512 in 16 x BK=32 double-buffered tiles.
// TMA (SW128) staging driven by one elected thread; raw fp32 in SMEM (HW truncates to tf32).
// Final MMA completion is consumed by the elected thread only; everyone else gates on
// __syncthreads() so no warp touches TMEM early (and no diverged-warp tcgen05.ld).

static constexpr int THREADS = 512;
static constexpr int NKT = 16;          // 512 / 32
static constexpr float EPSV = 1e-5f;
static constexpr unsigned TILE_TX = 16384u + 65536u;   // A (16KB) + B (64KB) per K-tile

// shared memory layout (dynamic) — tcgen05 path
static constexpr int SM_TMEM  = 0;
static constexpr int SM_FULL0 = 8;                  // TMA-complete mbar, buffer 0
static constexpr int SM_FULL1 = 16;
static constexpr int SM_MMA0  = 24;                 // MMA-done mbar, buffer 0
static constexpr int SM_MMA1  = 32;
static constexpr int SM_RED0 = 64;                  // 512 floats
static constexpr int SM_RED1 = SM_RED0 + 2048;      // 512 floats
static constexpr int SM_B1v  = SM_RED1 + 2048;      // 512 floats
static constexpr int SM_G    = SM_B1v + 2048;       // 512 floats
static constexpr int SM_BE   = SM_G + 2048;         // 512 floats
static constexpr int SM_A0   = 16384;               // 2 x 16KB A tiles (128 x 32 fp32)
static constexpr int SM_BT0  = 49152;               // 2 x 64KB B tiles (512 x 32 fp32)
static constexpr int SMEM_TOTAL = SM_BT0 + 2 * 65536;  // 180224 bytes

// Arch-specific ("a") feature fence: tcgen05/TMEM only exist on sm_10xa passes.
#if defined(__CUDA_ARCH__) && (defined(__CUDA_ARCH_FEAT_SM103_ALL) || \
                               defined(__CUDA_ARCH_FEAT_SM100_ALL) || \
                               defined(__CUDA_ARCH_FEAT_SM101_ALL) || \
                               defined(__CUDA_ARCH_SPECIFIC__)     || \
                               defined(__CUDA_ARCH_FAMILY_SPECIFIC__))
#define RH_TCGEN05 1
#else
#define RH_TCGEN05 0
#endif

#if RH_TCGEN05

// idesc: c=F32(1<<4), a=TF32(2<<7), b=TF32(2<<10), N=256 (32<<17), M=128 (8<<24)
static constexpr uint32_t IDESC_TF32 =
    (1u << 4) | (2u << 7) | (2u << 10) | (32u << 17) | (8u << 24);

// SW128 K-major descriptor base: layout=2, version=1, SBO=64 (1024B atom), LBO=1
static constexpr uint64_t DESC_BASE_SW128 =
    (uint64_t(2) << 61) | (uint64_t(1) << 46) | (uint64_t(64) << 32) | (uint64_t(1) << 16);

static __device__ __forceinline__ uint32_t smem_u32(const void* p) {
    uint32_t a;
    asm("{ .reg .u64 t; cvta.to.shared.u64 t, %1; cvt.u32.u64 %0, t; }" : "=r"(a) : "l"(p));
    return a;
}
static __device__ __forceinline__ uint64_t make_desc(uint32_t addr) {
    return DESC_BASE_SW128 | ((uint64_t)(addr >> 4) & 0x3FFF);
}
static __device__ __forceinline__ bool elect_one() {
    uint32_t p;
    asm volatile("{\n\t.reg .pred P;\n\telect.sync _|P, 0xFFFFFFFF;\n\tselp.b32 %0, 1, 0, P;\n\t}"
                 : "=r"(p));
    return p != 0;
}
static __device__ __forceinline__ void mbar_init(uint32_t a, uint32_t cnt) {
    asm volatile("mbarrier.init.shared.b64 [%0], %1;" :: "r"(a), "r"(cnt) : "memory");
}
static __device__ __forceinline__ void mbar_inval(uint32_t a) {
    asm volatile("mbarrier.inval.shared.b64 [%0];" :: "r"(a) : "memory");
}
static __device__ __forceinline__ void mbar_expect_tx(uint32_t a, uint32_t tx) {
    asm volatile("mbarrier.arrive.expect_tx.shared.b64 _, [%0], %1;" :: "r"(a), "r"(tx) : "memory");
}
static __device__ __forceinline__ void mbar_wait(uint32_t a, uint32_t parity) {
    asm volatile(
        "{\n\t.reg .pred P;\n\t"
        "W%=:\n\t"
        "mbarrier.try_wait.parity.acquire.cta.shared::cta.b64 P, [%0], %1, 0x989680;\n\t"
        "@P bra.uni D%=;\n\t"
        "bra.uni W%=;\n\t"
        "D%=:\n\t}"
        :: "r"(a), "r"(parity) : "memory");
}
static __device__ __forceinline__ void tma_2d(uint32_t dst, const CUtensorMap* m,
                                              int c0, int c1, uint32_t mbar) {
    asm volatile(
        "cp.async.bulk.tensor.2d.shared::cta.global.tile.mbarrier::complete_tx::bytes "
        "[%0], [%1, {%2, %3}], [%4];"
        :: "r"(dst), "l"(m), "r"(c0), "r"(c1), "r"(mbar) : "memory");
}
static __device__ __forceinline__ void tmem_alloc_512(uint32_t smem_dst) {
    asm volatile("tcgen05.alloc.cta_group::1.sync.aligned.shared::cta.b32 [%0], %1;"
                 :: "r"(smem_dst), "r"(512u) : "memory");
}
static __device__ __forceinline__ void tmem_dealloc_512(uint32_t tmem) {
    asm volatile("tcgen05.dealloc.cta_group::1.sync.aligned.b32 %0, %1;" :: "r"(tmem), "r"(512u));
}
static __device__ __forceinline__ void tmem_relinquish() {
    asm volatile("tcgen05.relinquish_alloc_permit.cta_group::1.sync.aligned;");
}
static __device__ __forceinline__ void mma_tf32_ss(uint32_t d, uint64_t ad, uint64_t bd,
                                                   uint32_t idesc, uint32_t en) {
    asm volatile(
        "{\n\t.reg .pred p;\n\tsetp.ne.u32 p, %4, 0;\n\t"
        "tcgen05.mma.cta_group::1.kind::tf32 [%0], %1, %2, %3, p;\n\t}"
        :: "r"(d), "l"(ad), "l"(bd), "r"(idesc), "r"(en) : "memory");
}
static __device__ __forceinline__ void mma_commit(uint32_t mbar) {
    asm volatile("tcgen05.commit.cta_group::1.mbarrier::arrive::one.shared::cluster.b64 [%0];"
                 :: "r"(mbar) : "memory");
}
static __device__ __forceinline__ void tmem_wait_ld() {
    asm volatile("tcgen05.wait::ld.sync.aligned;" ::: "memory");
}

#define LDTM_X32(r, addr)                                                      \
    asm volatile(                                                              \
        "tcgen05.ld.sync.aligned.32x32b.x32.b32 "                              \
        "{%0, %1, %2, %3, %4, %5, %6, %7, "                                    \
        " %8, %9, %10, %11, %12, %13, %14, %15, "                              \
        " %16, %17, %18, %19, %20, %21, %22, %23, "                            \
        " %24, %25, %26, %27, %28, %29, %30, %31}, [%32];"                     \
        : "=r"((r)[0]),  "=r"((r)[1]),  "=r"((r)[2]),  "=r"((r)[3]),           \
          "=r"((r)[4]),  "=r"((r)[5]),  "=r"((r)[6]),  "=r"((r)[7]),           \
          "=r"((r)[8]),  "=r"((r)[9]),  "=r"((r)[10]), "=r"((r)[11]),          \
          "=r"((r)[12]), "=r"((r)[13]), "=r"((r)[14]), "=r"((r)[15]),          \
          "=r"((r)[16]), "=r"((r)[17]), "=r"((r)[18]), "=r"((r)[19]),          \
          "=r"((r)[20]), "=r"((r)[21]), "=r"((r)[22]), "=r"((r)[23]),          \
          "=r"((r)[24]), "=r"((r)[25]), "=r"((r)[26]), "=r"((r)[27]),          \
          "=r"((r)[28]), "=r"((r)[29]), "=r"((r)[30]), "=r"((r)[31])           \
        : "r"(addr))

#endif  // RH_TCGEN05

__global__ void __launch_bounds__(THREADS, 1)
fused_head_kernel(const float* __restrict__ x, const float* __restrict__ W1,
                  const float* __restrict__ b1, const float* __restrict__ gamma,
                  const float* __restrict__ beta, const float* __restrict__ Wout,
                  const float* __restrict__ bout, float* __restrict__ out,
                  const __grid_constant__ CUtensorMap tmx,
                  const __grid_constant__ CUtensorMap tmw)
{
    extern __shared__ char smem[];
    const int tid = threadIdx.x;
    const int wid = tid >> 5;
    const int lid = tid & 31;
    const int bx = blockIdx.x;
    const int bb = bx >> 2;               // batch index
    const int t0 = (bx & 3) << 7;         // first t of this CTA's 128 rows

#if RH_TCGEN05
    const uint32_t sb = smem_u32(smem);
    const int xrow0 = bb * 513 + t0;      // first global row of x for this CTA

    if (wid == 0) tmem_alloc_512(sb + SM_TMEM);
    if (tid == 0) {
        mbar_init(sb + SM_FULL0, 1);
        mbar_init(sb + SM_FULL1, 1);
        mbar_init(sb + SM_MMA0, 1);
        mbar_init(sb + SM_MMA1, 1);
    }

    float* smb1 = (float*)(smem + SM_B1v);
    float* smg  = (float*)(smem + SM_G);
    float* smbe = (float*)(smem + SM_BE);
    smb1[tid] = b1[tid];
    smg[tid]  = gamma[tid];
    smbe[tid] = beta[tid];
    __syncthreads();                      // mbar init + smem consts visible
    const uint32_t tmem = *(const uint32_t*)(smem + SM_TMEM);

    // ---- mainloop: driven entirely by one elected thread of warp 0 ----
    if (wid == 0) {
        if (elect_one()) {
            uint32_t pf[2] = {0, 0}, pm[2] = {0, 0};

            // prologue: K-tile 0 into buffer 0
            mbar_expect_tx(sb + SM_FULL0, TILE_TX);
            tma_2d(sb + SM_A0,            &tmx, 0, xrow0, sb + SM_FULL0);
            tma_2d(sb + SM_BT0,           &tmw, 0, 0,     sb + SM_FULL0);
            tma_2d(sb + SM_BT0 + 32768,   &tmw, 0, 256,   sb + SM_FULL0);

            for (int k = 0; k < NKT; k++) {
                const int j = k & 1;
                mbar_wait(sb + (j ? SM_FULL1 : SM_FULL0), pf[j] & 1);
                pf[j]++;

                const uint64_t ad = make_desc(sb + SM_A0 + j * 16384);
                const uint64_t bd = make_desc(sb + SM_BT0 + j * 65536);
#pragma unroll
                for (int c = 0; c < 4; c++) {             // 4 K-steps of 8 within BK=32
                    const uint32_t en = (k | c) ? 1u : 0u;
                    mma_tf32_ss(tmem,       ad + c * 2, bd + c * 2,        IDESC_TF32, en);
                    mma_tf32_ss(tmem + 256, ad + c * 2, bd + 2048 + c * 2, IDESC_TF32, en);
                }
                mma_commit(sb + (j ? SM_MMA1 : SM_MMA0));

                if (k + 1 < NKT) {
                    const int jn = j ^ 1;
                    if (k >= 1) {         // buffer jn last used by MMA of iter k-1
                        mbar_wait(sb + (jn ? SM_MMA1 : SM_MMA0), pm[jn] & 1);
                        pm[jn]++;
                    }
                    const uint32_t fb = sb + (jn ? SM_FULL1 : SM_FULL0);
                    mbar_expect_tx(fb, TILE_TX);
                    const int c0 = (k + 1) * 32;
                    tma_2d(sb + SM_A0 + jn * 16384,          &tmx, c0, xrow0, fb);
                    tma_2d(sb + SM_BT0 + jn * 65536,         &tmw, c0, 0,     fb);
                    tma_2d(sb + SM_BT0 + jn * 65536 + 32768, &tmw, c0, 256,   fb);
                }
            }
            // Final MMA completion consumed ONLY here (phase 7 of SM_MMA1, parity 1);
            // this thread tracked every phase, so the parity wait is within one phase.
            mbar_wait(sb + SM_MMA1, pm[1] & 1);
        }
    }

    // Gate everyone on the elected thread having observed the final commit.
    // (No early TMEM reads; warp 0 reconverges before this barrier.)
    __syncthreads();
    asm volatile("tcgen05.fence::after_thread_sync;" ::: "memory");

    // ---- fused epilogue (16 warps): bias + LN stats + normalize + ReLU + Wout dot ----
    const int sub  = wid & 3;            // TMEM subpartition
    const int qtr  = wid >> 2;           // column quarter (0..3): cols [qtr*128, qtr*128+128)
    const int lrow = (sub << 5) + lid;   // row within CTA tile (0..127)
    const int trow = t0 + lrow;
    const uint32_t tb = tmem + qtr * 128;
    float* red0 = (float*)(smem + SM_RED0);
    float* red1 = (float*)(smem + SM_RED1);

    // pass 1: sum / sumsq over this warp's column quarter
    float sum = 0.f, sq = 0.f;
#pragma unroll
    for (int cb = 0; cb < 128; cb += 32) {
        uint32_t r[32];
        LDTM_X32(r, tb + cb);
        tmem_wait_ld();
#pragma unroll
        for (int i = 0; i < 32; i++) {
            float v = __uint_as_float(r[i]) + smb1[qtr * 128 + cb + i];
            sum += v;
            sq  = fmaf(v, v, sq);
        }
    }
    red0[qtr * 128 + lrow] = sum;
    red1[qtr * 128 + lrow] = sq;
    __syncthreads();
    const float s  = red0[lrow] + red0[128 + lrow] + red0[256 + lrow] + red0[384 + lrow];
    const float q  = red1[lrow] + red1[128 + lrow] + red1[256 + lrow] + red1[384 + lrow];
    const float mu = s * (1.f / 512.f);
    const float var = q * (1.f / 512.f) - mu * mu;
    const float rstd = rsqrtf(var + EPSV);

    // pass 2: normalize, ReLU, dot with Wout[trow]
    float acc = 0.f;
    const float4* wr = (const float4*)(Wout + (size_t)trow * 512 + qtr * 128);
#pragma unroll
    for (int cb = 0; cb < 128; cb += 32) {
        uint32_t r[32];
        LDTM_X32(r, tb + cb);
        tmem_wait_ld();
#pragma unroll
        for (int i4 = 0; i4 < 8; i4++) {
            float4 w = wr[(cb >> 2) + i4];
#pragma unroll
            for (int u = 0; u < 4; u++) {
                const int e = qtr * 128 + cb + i4 * 4 + u;
                float v = __uint_as_float(r[i4 * 4 + u]) + smb1[e];
                float n = fmaf((v - mu) * rstd, smg[e], smbe[e]);
                n = fmaxf(n, 0.f);
                const float wv = (u == 0) ? w.x : (u == 1) ? w.y : (u == 2) ? w.z : w.w;
                acc = fmaf(n, wv, acc);
            }
        }
    }
    __syncthreads();                 // red reads above complete before overwrite
    red0[qtr * 128 + lrow] = acc;
    __syncthreads();
    if (qtr == 0) {
        out[(size_t)bx * 128 + lrow] =
            red0[lrow] + red0[128 + lrow] + red0[256 + lrow] + red0[384 + lrow] + bout[trow];
    }

    __syncthreads();
    if (tid == 0) {
        mbar_inval(sb + SM_FULL0);
        mbar_inval(sb + SM_FULL1);
        mbar_inval(sb + SM_MMA0);
        mbar_inval(sb + SM_MMA1);
    }
    if (wid == 0) {
        tmem_relinquish();
        tmem_dealloc_512(tmem);
    }

#else  // ---------- SIMT fp32 fallback (non-arch-specific device passes) ----------

    const float* xbase = x + ((size_t)bb * 513 + t0) * 512;
    float* xs = (float*)smem;              // 16 x 512 floats
    float* hs = xs + 16 * 512;             // 16 x 512 floats

    for (int rc = 0; rc < 128; rc += 16) {
        for (int i = tid; i < 16 * 512; i += THREADS)
            xs[i] = xbase[((size_t)(rc + (i >> 9))) * 512 + (i & 511)];
        __syncthreads();

        for (int idx = tid; idx < 16 * 512; idx += THREADS) {
            const int c = idx >> 4;
            const int r = idx & 15;
            const float* xr = xs + r * 512;
            const float* wc = W1 + (size_t)c * 512;
            float acc = 0.f;
#pragma unroll 4
            for (int k2 = 0; k2 < 512; k2++) acc = fmaf(xr[k2], wc[k2], acc);
            hs[r * 512 + c] = acc + b1[c];
        }
        __syncthreads();

        for (int rr = wid; rr < 16; rr += 16) {
            const float* hr = hs + rr * 512;
            float s = 0.f, q = 0.f;
            for (int k2 = lid; k2 < 512; k2 += 32) {
                float v = hr[k2];
                s += v;
                q = fmaf(v, v, q);
            }
#pragma unroll
            for (int off = 16; off; off >>= 1) {
                s += __shfl_xor_sync(0xFFFFFFFFu, s, off);
                q += __shfl_xor_sync(0xFFFFFFFFu, q, off);
            }
            const float mu = s * (1.f / 512.f);
            const float var = q * (1.f / 512.f) - mu * mu;
            const float rstd = rsqrtf(var + EPSV);
            const int trow = t0 + rc + rr;
            float a = 0.f;
            for (int k2 = lid; k2 < 512; k2 += 32) {
                float v = hr[k2];
                float n = fmaf((v - mu) * rstd, gamma[k2], beta[k2]);
                n = fmaxf(n, 0.f);
                a = fmaf(n, Wout[(size_t)trow * 512 + k2], a);
            }
#pragma unroll
            for (int off = 16; off; off >>= 1)
                a += __shfl_xor_sync(0xFFFFFFFFu, a, off);
            if (lid == 0) out[(size_t)bx * 128 + rc + rr] = a + bout[trow];
        }
        __syncthreads();
    }
#endif
}

typedef CUresult (*PFN_encodeTiled)(CUtensorMap*, CUtensorMapDataType, cuuint32_t, void*,
                                    const cuuint64_t*, const cuuint64_t*, const cuuint32_t*,
                                    const cuuint32_t*, CUtensorMapInterleave, CUtensorMapSwizzle,
                                    CUtensorMapL2promotion, CUtensorMapFloatOOBfill);

static void encode_2d(PFN_encodeTiled enc, CUtensorMap* m, const void* base,
                      unsigned long long d0, unsigned long long d1,
                      unsigned box0, unsigned box1) {
    cuuint64_t dims[2]    = {d0, d1};
    cuuint64_t strides[1] = {d0 * 4ull};
    cuuint32_t box[2]     = {box0, box1};
    cuuint32_t es[2]      = {1, 1};
    enc(m, CU_TENSOR_MAP_DATA_TYPE_FLOAT32, 2, const_cast<void*>(base),
        dims, strides, box, es,
        CU_TENSOR_MAP_INTERLEAVE_NONE, CU_TENSOR_MAP_SWIZZLE_128B,
        CU_TENSOR_MAP_L2_PROMOTION_L2_128B, CU_TENSOR_MAP_FLOAT_OOB_FILL_NONE);
}

extern "C" void kernel_launch(void* const* d_in, const int* in_sizes, int n_in,
                              void* d_out, int out_size) {
    (void)in_sizes; (void)n_in; (void)out_size;
    const float* x     = (const float*)d_in[0];
    const float* W1    = (const float*)d_in[1];
    const float* b1    = (const float*)d_in[2];
    const float* gamma = (const float*)d_in[3];
    const float* beta  = (const float*)d_in[4];
    const float* Wout  = (const float*)d_in[5];
    const float* bout  = (const float*)d_in[6];
    float* out = (float*)d_out;

    // Driver entry point via runtime API (no -lcuda link dependency).
    PFN_encodeTiled enc = nullptr;
    cudaDriverEntryPointQueryResult st;
    cudaGetDriverEntryPoint("cuTensorMapEncodeTiled", (void**)&enc, cudaEnableDefault, &st);

    CUtensorMap tmx, tmw;
    encode_2d(enc, &tmx, x,  512ull, 256ull * 513ull, 32u, 128u);  // x:  [131328, 512] fp32
    encode_2d(enc, &tmw, W1, 512ull, 512ull,          32u, 256u);  // W1: [512, 512]   fp32

    cudaFuncSetAttribute(fused_head_kernel,
                         cudaFuncAttributeMaxDynamicSharedMemorySize, SMEM_TOTAL);
    fused_head_kernel<<<1024, THREADS, SMEM_TOTAL>>>(x, W1, b1, gamma, beta, Wout, bout, out,
                                                     tmx, tmw);
}